// round 17
// baseline (speedup 1.0000x reference)
#include <cuda_runtime.h>
#include <cuda_bf16.h>
#include <math.h>
#include <stdint.h>

#define NSPEC   7
#define NAT_TOT 2048
#define DAEV    1008

// ---- persistent scratch (fragment-packed: 8x8 bf16 = 128B blocks, [n8][k8] order) ----
__device__ __nv_bfloat16 g_aevA[NSPEC * 32 * 64 * 1024];  // [slot][kc32][64x32 packed]
__device__ __nv_bfloat16 g_B0[56 * 32 * 8192];            // [es][kc32][256x32 packed]
__device__ __nv_bfloat16 g_B1[56 * 8 * 6144];             // [es][kc8 ][192x32 packed]
__device__ __nv_bfloat16 g_B2[56 * 6 * 6144];             // [es][kc6 ][192x32 packed] (n>=160 zero)
__device__ int g_bucket[NSPEC * NAT_TOT];
__device__ int g_pos[NAT_TOT];
__device__ int g_cnt[NSPEC];
__device__ int g_pj[496], g_pk[496];

// ---- helpers ----
__device__ __forceinline__ float celu01(float x) {
    return x > 0.f ? x : 0.1f * (__expf(x * 10.f) - 1.f);
}
__device__ __forceinline__ uint32_t smem_u32(const void* p) {
    uint32_t a;
    asm("{ .reg .u64 t; cvta.to.shared.u64 t, %1; cvt.u32.u64 %0, t; }" : "=r"(a) : "l"(p));
    return a;
}
__device__ __forceinline__ void cpasync16(uint32_t dst, const void* src) {
    asm volatile("cp.async.cg.shared.global [%0], [%1], 16;" :: "r"(dst), "l"(src));
}
__device__ __forceinline__ void mma16(float* d, uint32_t a0, uint32_t a1,
                                      uint32_t a2, uint32_t a3,
                                      uint32_t b0, uint32_t b1) {
    asm volatile(
        "mma.sync.aligned.m16n8k16.row.col.f32.bf16.bf16.f32 "
        "{%0,%1,%2,%3},{%4,%5,%6,%7},{%8,%9},{%0,%1,%2,%3};"
        : "+f"(d[0]), "+f"(d[1]), "+f"(d[2]), "+f"(d[3])
        : "r"(a0), "r"(a1), "r"(a2), "r"(a3), "r"(b0), "r"(b1));
}
#define LDSM4(r0, r1, r2, r3, addr) \
    asm volatile("ldmatrix.sync.aligned.m8n8.x4.shared.b16 {%0,%1,%2,%3}, [%4];" \
                 : "=r"(r0), "=r"(r1), "=r"(r2), "=r"(r3) : "r"(addr))
__device__ __forceinline__ uint32_t packbf2(float x, float y) {
    __nv_bfloat162 v = __floats2bfloat162_rn(x, y);
    return *(uint32_t*)&v;
}

// =================== fused setup: init + pair table + bucket ===================
__global__ void __launch_bounds__(512)
k_setup(const int* __restrict__ species, const float* __restrict__ sae,
        float* __restrict__ out) {
    __shared__ int scnt[NSPEC];
    int t = threadIdx.x;
    if (t < 64)    out[t] = 0.f;
    if (t < NSPEC) scnt[t] = 0;
    if (t < 496) {
        int kk = (int)((1.f + sqrtf(1.f + 8.f * (float)t)) * 0.5f);
        while (kk * (kk - 1) / 2 > t) kk--;
        while ((kk + 1) * kk / 2 <= t) kk++;
        g_pj[t] = t - kk * (kk - 1) / 2;
        g_pk[t] = kk;
    }
    __syncthreads();
    #pragma unroll
    for (int a = t; a < NAT_TOT; a += 512) {
        int s = species[a];
        int idx = atomicAdd(&scnt[s], 1);
        g_bucket[s * NAT_TOT + idx] = a;
        g_pos[a] = idx;
        atomicAdd(&out[a >> 5], sae[s]);
    }
    __syncthreads();
    if (t < NSPEC) g_cnt[t] = scnt[t];
}

// transpose W[k][n] -> fragment-packed [n8][k8] 8x8 blocks, bf16 (coalesced 16B writes)
__global__ void __launch_bounds__(256)
k_prep(const float* __restrict__ W0, const float* __restrict__ W1,
       const float* __restrict__ W2) {
    __shared__ float st[32 * 257];
    int es = blockIdx.x, y = blockIdx.y, t = threadIdx.x;
    const float* src; __nv_bfloat16* dst; int N, Nst, Ktot, k0;
    if (y < 32)      { N = 256; Nst = 256; Ktot = 1008; k0 = y * 32;
                       src = W0 + (size_t)es * 1008 * 256;
                       dst = g_B0 + (size_t)(es * 32 + y) * 8192; }
    else if (y < 40) { N = 192; Nst = 192; Ktot = 256; k0 = (y - 32) * 32;
                       src = W1 + (size_t)es * 256 * 192;
                       dst = g_B1 + (size_t)(es * 8 + (y - 32)) * 6144; }
    else             { N = 160; Nst = 192; Ktot = 192; k0 = (y - 40) * 32;
                       src = W2 + (size_t)es * 192 * 160;
                       dst = g_B2 + (size_t)(es * 6 + (y - 40)) * 6144; }
    int n4c = N / 4;
    for (int idx4 = t; idx4 < 32 * n4c; idx4 += 256) {
        int k = idx4 / n4c, n4 = (idx4 - k * n4c) * 4;
        float4 v = (k0 + k < Ktot) ? *(const float4*)(src + (size_t)(k0 + k) * N + n4)
                                   : make_float4(0.f, 0.f, 0.f, 0.f);
        st[k * 257 + n4 + 0] = v.x;
        st[k * 257 + n4 + 1] = v.y;
        st[k * 257 + n4 + 2] = v.z;
        st[k * 257 + n4 + 3] = v.w;
    }
    __syncthreads();
    for (int u = t; u < Nst * 4; u += 256) {
        int frag = u >> 3, n8 = u & 7;
        int nn = (frag >> 2) * 8 + n8;
        int k8 = frag & 3;
        uint32_t w[4];
        #pragma unroll
        for (int q = 0; q < 4; q++) {
            float x0 = (nn < N) ? st[(k8 * 8 + 2 * q) * 257 + nn] : 0.f;
            float x1 = (nn < N) ? st[(k8 * 8 + 2 * q + 1) * 257 + nn] : 0.f;
            w[q] = packbf2(x0, x1);
        }
        *(uint4*)((char*)dst + u * 16) = *(uint4*)w;
    }
}

// AEV builder with neighbor-compacted angular pairs -> fragment-packed bf16 A tiles
__global__ void __launch_bounds__(256)
k_aev(const int* __restrict__ species, const float* __restrict__ coords) {
    int bi = blockIdx.x;
    int b = bi >> 5, i = bi & 31;
    __shared__ float px[32], py[32], pz[32];
    __shared__ float dist[32], fcr[32], fca[32], ux[32], uy[32], uz[32];
    __shared__ int   sp[32];
    __shared__ int   nbr[32];
    __shared__ int   s_npairs;
    __shared__ float radterm[512];
    __shared__ __align__(16) float f1s[496 * 4];
    __shared__ __align__(16) float f2s[496 * 8];
    __shared__ int   ptype[496];
    __shared__ int   order[496];
    __shared__ int   tcnt[28], toff[28];
    __shared__ __align__(16) float aev[DAEV];
    int t = threadIdx.x;

    if (t < 32) {
        px[t] = coords[(b * 32 + t) * 3 + 0];
        py[t] = coords[(b * 32 + t) * 3 + 1];
        pz[t] = coords[(b * 32 + t) * 3 + 2];
        sp[t] = species[b * 32 + t];
    }
    if (t >= 32 && t < 60) tcnt[t - 32] = 0;
    __syncthreads();

    if (t < 32) {
        float dx = px[t] - px[i], dy = py[t] - py[i], dz = pz[t] - pz[i];
        float d = sqrtf(dx * dx + dy * dy + dz * dz + 1e-12f);
        dist[t] = d;
        float inv = 1.f / d;
        ux[t] = dx * inv; uy[t] = dy * inv; uz[t] = dz * inv;
        const float PI = 3.14159265358979f;
        fcr[t] = (t != i && d < 5.1f) ? 0.5f * __cosf(PI * d / 5.1f) + 0.5f : 0.f;
        float fa = (t != i && d < 3.5f) ? 0.5f * __cosf(PI * d / 3.5f) + 0.5f : 0.f;
        fca[t] = fa;
        bool act = fa > 0.f;
        unsigned mask = __ballot_sync(0xffffffffu, act);
        int rank = __popc(mask & ((1u << t) - 1u));
        if (act) nbr[rank] = t;
        if (t == 0) {
            int nn = __popc(mask);
            s_npairs = nn * (nn - 1) / 2;
        }
    }
    __syncthreads();
    int npairs = s_npairs;

    for (int k = t; k < 512; k += 256) {
        int j = k >> 4, r = k & 15;
        float fr = fcr[j];
        float x = dist[j] - (0.8f + 0.26875f * (float)r);
        radterm[k] = (fr > 0.f) ? 0.25f * __expf(-19.7f * x * x) * fr : 0.f;
    }

    const float czv[4] = { 0.9238795325f,  0.3826834324f, -0.3826834324f, -0.9238795325f };
    const float szv[4] = { 0.3826834324f,  0.9238795325f,  0.9238795325f,  0.3826834324f };
    for (int p = t; p < npairs; p += 256) {
        int j = nbr[g_pj[p]], kk = nbr[g_pk[p]];
        int pa = min(sp[j], sp[kk]), pb = max(sp[j], sp[kk]);
        int ty = pa * 7 - (pa * (pa - 1)) / 2 + (pb - pa);
        ptype[p] = ty;
        atomicAdd(&tcnt[ty], 1);
        float w = 2.f * fca[j] * fca[kk];
        float cv = ux[j] * ux[kk] + uy[j] * uy[kk] + uz[j] * uz[kk];
        float ct = 0.95f * fminf(1.f, fmaxf(-1.f, cv));
        float stv = sqrtf(fmaxf(0.f, 1.f - ct * ct));
        float avg = 0.5f * (dist[j] + dist[kk]);
        #pragma unroll
        for (int a2 = 0; a2 < 8; a2++) {
            float x = avg - (0.8f + 0.3375f * (float)a2);
            f2s[p * 8 + a2] = __expf(-12.5f * x * x) * w;
        }
        #pragma unroll
        for (int z = 0; z < 4; z++) {
            float c = (1.f + ct * czv[z] + stv * szv[z]) * 0.5f;
            f1s[p * 4 + z] = (c > 1e-30f) ? exp2f(14.1f * __log2f(c)) : 0.f;
        }
    }
    __syncthreads();

    if (t == 0) {
        int run = 0;
        for (int ty = 0; ty < 28; ty++) { toff[ty] = run; run += tcnt[ty]; tcnt[ty] = toff[ty]; }
    }
    __syncthreads();

    for (int p = t; p < npairs; p += 256) {
        int idx = atomicAdd(&tcnt[ptype[p]], 1);
        order[idx] = p;
    }
    __syncthreads();

    if (t < 112) {
        int s = t >> 4, r = t & 15;
        float sum = 0.f;
        #pragma unroll
        for (int j = 0; j < 32; j++)
            sum += (sp[j] == s) ? radterm[j * 16 + r] : 0.f;
        aev[t] = sum;
    }

    if (t < 224) {
        int u = t;
        int ty = u >> 3, r8 = u & 7, z = r8 >> 1, g = r8 & 1;
        int beg = toff[ty], end = tcnt[ty];
        float4 sum = make_float4(0.f, 0.f, 0.f, 0.f);
        for (int q = beg; q < end; q++) {
            int p = order[q];
            float f1 = f1s[p * 4 + z];
            float4 v = *(const float4*)&f2s[p * 8 + g * 4];
            sum.x = fmaf(f1, v.x, sum.x);
            sum.y = fmaf(f1, v.y, sum.y);
            sum.z = fmaf(f1, v.z, sum.z);
            sum.w = fmaf(f1, v.w, sum.w);
        }
        *(float4*)&aev[112 + ty * 32 + z * 8 + g * 4] = sum;
    }
    __syncthreads();

    if (t < 128) {
        int si  = sp[i];
        int idx = g_pos[b * 32 + i];
        int slot = si * 32 + (idx >> 6);
        int m    = idx & 63;
        __nv_bfloat16* dst = g_aevA + (size_t)slot * 65536;
        int mo = (m >> 3) * 256 + (m & 7) * 8;
        int kc = t >> 2, k8 = t & 3;
        int kbase = kc * 32 + k8 * 8;
        uint32_t w[4];
        #pragma unroll
        for (int q = 0; q < 4; q++) {
            float x0 = (kbase + 2 * q     < DAEV) ? aev[kbase + 2 * q]     : 0.f;
            float x1 = (kbase + 2 * q + 1 < DAEV) ? aev[kbase + 2 * q + 1] : 0.f;
            w[q] = packbf2(x0, x1);
        }
        *(uint4*)(dst + kc * 2048 + mo + k8 * 64) = *(uint4*)w;
    }
}

// =================== bf16 mma MLP: 2-kc quanta, 2-stage, 23 barriers total ===================
// Layer-0 stages ALIAS the H0/H1 region (stages dead before H0 epilogue writes):
//   SA: 2 stages x 8192B at [0, 16384)
//   SB: 2 stages x 32768B at [16384, 81920)
// H0 (row 528B, 33792B) written at 0 after layer-0 mainloop.
// H1 (row 400B, 25600B) at 33792. Layers 1-2 B stages: 2 x 24576B at [59392, 108544).
#define H0B   0
#define H1B   33792
#define SB12  59392    // layer1/2 B stages
#define B0B   108544   // 256 f
#define B1B   109568   // 192 f
#define B2B   110336   // 160 f
#define W3B   110976   // 160 f
#define ATB   111616   // 64 int
#define SMEM_BYTES 112000

__global__ void __launch_bounds__(256, 2)
k_mlp(const float* __restrict__ b0, const float* __restrict__ b1,
      const float* __restrict__ b2, const float* __restrict__ b3,
      const float* __restrict__ W3, float* __restrict__ out) {
    int es = blockIdx.x, s = es % 7;
    int n = g_cnt[s];
    int m0 = blockIdx.y * 64;
    if (m0 >= n) return;

    extern __shared__ __align__(16) char smc[];
    int t = threadIdx.x, wid = t >> 5, lane = t & 31;
    int wm = wid >> 1, wn = wid & 1;         // 4x2 warp grid (layers 1-2)
    int wm2 = wid >> 2, wn4 = wid & 3;       // 2x4 warp grid (layer 0)
    int qr = lane >> 2, qc = lane & 3;
    int g = lane >> 3, r = lane & 7;
    uint32_t smb = smem_u32(smc);
    float* b0f = (float*)(smc + B0B);
    float* b1f = (float*)(smc + B1B);
    float* b2f = (float*)(smc + B2B);
    float* W3f = (float*)(smc + W3B);
    int* atoms = (int*)(smc + ATB);

    if (t < 256) b0f[t] = b0[es * 256 + t];
    if (t < 192) b1f[t] = b1[es * 192 + t];
    if (t < 160) b2f[t] = b2[es * 160 + t];
    if (t < 160) W3f[t] = W3[es * 160 + t];
    if (t < 64)  atoms[t] = (m0 + t < n) ? g_bucket[s * NAT_TOT + m0 + t] : -1;
    float b3v = b3[es];
    __syncthreads();

    int slot = s * 32 + (int)blockIdx.y;
    const __nv_bfloat16* srcA  = g_aevA + (size_t)slot * 65536;
    const __nv_bfloat16* srcB0 = g_B0 + (size_t)es * 262144;
    const __nv_bfloat16* srcB1 = g_B1 + (size_t)es * 49152;
    const __nv_bfloat16* srcB2 = g_B2 + (size_t)es * 36864;

    int r0 = wm * 16 + qr;
    int aOffN = (g & 1) * 512 + (g >> 1) * 128 + r * 16;
    int bOffN = (g >> 1) * 512 + (g & 1) * 128 + r * 16;

    // ---------- layer 0: 1008 -> 256 (16 quanta of 2 kc; 2-stage) ----------
    {
        float acc[2][8][4] = {};
        {   // prefetch quantum 0 into stage 0
            #pragma unroll
            for (int i2 = 0; i2 < 2; i2++) {
                int idx = t + i2 * 256;
                cpasync16(smb + idx * 16, srcA + idx * 8);
            }
            #pragma unroll
            for (int i2 = 0; i2 < 8; i2++) {
                int idx = t + i2 * 256;
                cpasync16(smb + 16384 + idx * 16, srcB0 + idx * 8);
            }
            asm volatile("cp.async.commit_group;");
        }
        #pragma unroll
        for (int q = 0; q < 16; q++) {
            if (q == 15) asm volatile("cp.async.wait_group 0;");
            else         asm volatile("cp.async.wait_group 0;");   // G_q landed (issued 1 quantum ago)
            __syncthreads();
            if (q + 1 < 16) {
                int s2 = (q + 1) & 1;
                uint32_t sa = smb + s2 * 8192;
                uint32_t sb = smb + 16384 + s2 * 32768;
                const __nv_bfloat16* pA = srcA + (size_t)(q + 1) * 4096;
                const __nv_bfloat16* pB = srcB0 + (size_t)(q + 1) * 16384;
                #pragma unroll
                for (int i2 = 0; i2 < 2; i2++) {
                    int idx = t + i2 * 256;
                    cpasync16(sa + idx * 16, pA + idx * 8);
                }
                #pragma unroll
                for (int i2 = 0; i2 < 8; i2++) {
                    int idx = t + i2 * 256;
                    cpasync16(sb + idx * 16, pB + idx * 8);
                }
                asm volatile("cp.async.commit_group;");
            }
            int st = q & 1;
            uint32_t aQ = smb + st * 8192 + wm2 * 2048 + aOffN;
            uint32_t bQ = smb + 16384 + st * 32768 + wn4 * 4096 + bOffN;
            #pragma unroll
            for (int kb = 0; kb < 4; kb++) {
                int j = kb >> 1, kk = kb & 1;
                uint32_t aS = aQ + j * 4096 + kk * 256;
                uint32_t bS = bQ + j * 16384 + kk * 256;
                uint32_t a0, a1, a2, a3, a4, a5, a6, a7;
                LDSM4(a0, a1, a2, a3, aS);
                LDSM4(a4, a5, a6, a7, aS + 1024);
                #pragma unroll
                for (int nt = 0; nt < 4; nt++) {
                    uint32_t q0, q1, q2, q3;
                    LDSM4(q0, q1, q2, q3, bS + nt * 1024);
                    mma16(acc[0][2 * nt],     a0, a1, a2, a3, q0, q1);
                    mma16(acc[0][2 * nt + 1], a0, a1, a2, a3, q2, q3);
                    mma16(acc[1][2 * nt],     a4, a5, a6, a7, q0, q1);
                    mma16(acc[1][2 * nt + 1], a4, a5, a6, a7, q2, q3);
                }
            }
        }
        __syncthreads();   // stages dead; safe to write H0 over them
        uint32_t* H0w = (uint32_t*)(smc + H0B);
        #pragma unroll
        for (int mr = 0; mr < 2; mr++) {
            #pragma unroll
            for (int nx = 0; nx < 8; nx++) {
                int col = wn4 * 64 + nx * 8 + qc * 2;
                int row = wm2 * 32 + mr * 16 + qr;
                int ch = col >> 1;
                H0w[row * 132 + ch]       = packbf2(celu01(acc[mr][nx][0] + b0f[col]),
                                                    celu01(acc[mr][nx][1] + b0f[col + 1]));
                H0w[(row + 8) * 132 + ch] = packbf2(celu01(acc[mr][nx][2] + b0f[col]),
                                                    celu01(acc[mr][nx][3] + b0f[col + 1]));
            }
        }
    }
    __syncthreads();

    // ---------- layer 1: 256 -> 192 (A = H0 rows 528B; 4 quanta of 2 kc) ----------
    {
        float acc[12][4] = {};
        {   // prefetch quantum 0
            #pragma unroll
            for (int i2 = 0; i2 < 6; i2++) {
                int idx = t + i2 * 256;
                cpasync16(smb + SB12 + idx * 16, srcB1 + idx * 8);
            }
            asm volatile("cp.async.commit_group;");
        }
        uint32_t aBaseH = smb + H0B + (wm * 16 + (lane & 15)) * 528 + ((lane >> 4) * 8) * 2;
        #pragma unroll
        for (int q = 0; q < 4; q++) {
            asm volatile("cp.async.wait_group 0;");
            __syncthreads();
            if (q + 1 < 4) {
                int s2 = (q + 1) & 1;
                uint32_t sb = smb + SB12 + s2 * 24576;
                const __nv_bfloat16* pB = srcB1 + (size_t)(q + 1) * 12288;
                #pragma unroll
                for (int i2 = 0; i2 < 6; i2++) {
                    int idx = t + i2 * 256;
                    cpasync16(sb + idx * 16, pB + idx * 8);
                }
                asm volatile("cp.async.commit_group;");
            }
            int st = q & 1;
            uint32_t bQ = smb + SB12 + st * 24576 + wn * 6144 + bOffN;
            #pragma unroll
            for (int kb = 0; kb < 4; kb++) {
                int j = kb >> 1, kk = kb & 1;
                uint32_t a0, a1, a2, a3;
                LDSM4(a0, a1, a2, a3, aBaseH + q * 128 + kb * 32);
                uint32_t bS = bQ + j * 12288 + kk * 256;
                #pragma unroll
                for (int nt2 = 0; nt2 < 6; nt2++) {
                    uint32_t q0, q1, q2, q3;
                    LDSM4(q0, q1, q2, q3, bS + nt2 * 1024);
                    mma16(acc[2 * nt2],     a0, a1, a2, a3, q0, q1);
                    mma16(acc[2 * nt2 + 1], a0, a1, a2, a3, q2, q3);
                }
            }
        }
        __syncthreads();
        uint32_t* H1w = (uint32_t*)(smc + H1B);
        #pragma unroll
        for (int nt = 0; nt < 12; nt++) {
            int col = wn * 96 + nt * 8 + qc * 2;
            int ch = col >> 1;
            H1w[r0 * 100 + ch]       = packbf2(celu01(acc[nt][0] + b1f[col]),
                                               celu01(acc[nt][1] + b1f[col + 1]));
            H1w[(r0 + 8) * 100 + ch] = packbf2(celu01(acc[nt][2] + b1f[col]),
                                               celu01(acc[nt][3] + b1f[col + 1]));
        }
    }
    __syncthreads();

    // ---------- layer 2: 192 -> 160 (A = H1 rows 400B; 3 quanta of 2 kc; H2 -> H0B) ----------
    {
        float acc[12][4] = {};
        {
            #pragma unroll
            for (int i2 = 0; i2 < 6; i2++) {
                int idx = t + i2 * 256;
                cpasync16(smb + SB12 + idx * 16, srcB2 + idx * 8);
            }
            asm volatile("cp.async.commit_group;");
        }
        uint32_t aBaseH = smb + H1B + (wm * 16 + (lane & 15)) * 400 + ((lane >> 4) * 8) * 2;
        #pragma unroll
        for (int q = 0; q < 3; q++) {
            asm volatile("cp.async.wait_group 0;");
            __syncthreads();
            if (q + 1 < 3) {
                int s2 = (q + 1) & 1;
                uint32_t sb = smb + SB12 + s2 * 24576;
                const __nv_bfloat16* pB = srcB2 + (size_t)(q + 1) * 12288;
                #pragma unroll
                for (int i2 = 0; i2 < 6; i2++) {
                    int idx = t + i2 * 256;
                    cpasync16(sb + idx * 16, pB + idx * 8);
                }
                asm volatile("cp.async.commit_group;");
            }
            int st = q & 1;
            uint32_t bQ = smb + SB12 + st * 24576 + wn * 6144 + bOffN;
            #pragma unroll
            for (int kb = 0; kb < 4; kb++) {
                int j = kb >> 1, kk = kb & 1;
                uint32_t a0, a1, a2, a3;
                LDSM4(a0, a1, a2, a3, aBaseH + q * 128 + kb * 32);
                uint32_t bS = bQ + j * 12288 + kk * 256;
                #pragma unroll
                for (int nt2 = 0; nt2 < 6; nt2++) {
                    if (wn == 1 && nt2 >= 4) continue;   // cols >= 160 don't exist
                    uint32_t q0, q1, q2, q3;
                    LDSM4(q0, q1, q2, q3, bS + nt2 * 1024);
                    mma16(acc[2 * nt2],     a0, a1, a2, a3, q0, q1);
                    mma16(acc[2 * nt2 + 1], a0, a1, a2, a3, q2, q3);
                }
            }
        }
        __syncthreads();
        uint32_t* H2w = (uint32_t*)(smc + H0B);
        #pragma unroll
        for (int nt = 0; nt < 12; nt++) {
            if (wn == 1 && nt >= 8) continue;    // cols >= 160 don't exist
            int col = wn * 96 + nt * 8 + qc * 2;
            int ch = col >> 1;
            H2w[r0 * 84 + ch]       = packbf2(celu01(acc[nt][0] + b2f[col]),
                                              celu01(acc[nt][1] + b2f[col + 1]));
            H2w[(r0 + 8) * 84 + ch] = packbf2(celu01(acc[nt][2] + b2f[col]),
                                              celu01(acc[nt][3] + b2f[col + 1]));
        }
    }
    __syncthreads();

    // ---------- layer 3: 160 -> 1 ----------
    {
        const __nv_bfloat16* H2h = (const __nv_bfloat16*)(smc + H0B);
        for (int rr = 0; rr < 8; rr++) {
            int m = wid * 8 + rr;
            float p = 0.f;
            #pragma unroll
            for (int f = 0; f < 5; f++)
                p = fmaf(__bfloat162float(H2h[m * 168 + lane + f * 32]),
                         W3f[lane + f * 32], p);
            #pragma unroll
            for (int o = 16; o > 0; o >>= 1)
                p += __shfl_down_sync(0xffffffffu, p, o);
            if (lane == 0 && m0 + m < n) {
                int am = atoms[m];
                atomicAdd(&out[am >> 5], (p + b3v) * 0.125f);
            }
        }
    }
}

// =================== launcher (fork/join: prep overlaps setup+aev) ===================
extern "C" void kernel_launch(void* const* d_in, const int* in_sizes, int n_in,
                              void* d_out, int out_size) {
    const int*   species = (const int*)d_in[0];
    const float* coords  = (const float*)d_in[1];
    const float* W0 = (const float*)d_in[2];
    const float* b0 = (const float*)d_in[3];
    const float* W1 = (const float*)d_in[4];
    const float* b1 = (const float*)d_in[5];
    const float* W2 = (const float*)d_in[6];
    const float* b2 = (const float*)d_in[7];
    const float* W3 = (const float*)d_in[8];
    const float* b3 = (const float*)d_in[9];
    const float* sae = (const float*)d_in[10];
    float* out = (float*)d_out;

    static cudaStream_t s_prep = nullptr;
    static cudaEvent_t ev_fork = nullptr, ev_join = nullptr;
    if (s_prep == nullptr) {
        cudaStreamCreateWithFlags(&s_prep, cudaStreamNonBlocking);
        cudaEventCreateWithFlags(&ev_fork, cudaEventDisableTiming);
        cudaEventCreateWithFlags(&ev_join, cudaEventDisableTiming);
        cudaFuncSetAttribute(k_mlp, cudaFuncAttributeMaxDynamicSharedMemorySize, SMEM_BYTES);
    }

    // fork: prep on side stream
    cudaEventRecord(ev_fork, 0);
    cudaStreamWaitEvent(s_prep, ev_fork, 0);
    k_prep<<<dim3(56, 46), 256, 0, s_prep>>>(W0, W1, W2);
    cudaEventRecord(ev_join, s_prep);

    // main chain: fused setup, then AEV
    k_setup<<<1, 512>>>(species, sae, out);
    k_aev<<<NAT_TOT, 256>>>(species, coords);

    // join, then MLP
    cudaStreamWaitEvent(0, ev_join, 0);
    k_mlp<<<dim3(56, 12), 256, SMEM_BYTES>>>(b0, b1, b2, b3, W3, out);
}